// round 12
// baseline (speedup 1.0000x reference)
#include <cuda_runtime.h>
#include <cstdint>

// Shapes fixed for this problem
#define T_LEN   1024
#define NB      256
#define C_CLASS 128
#define S_TGT   128
#define NCF     (NB * C_CLASS)
#define ROWB    (NCF * 4)
#define NEGV    -1e30f
#define FULLM   0xffffffffu
// SLACK=5: wavefront crosses <=8 lanes per 8-step block, each hop amplifying
// by e^SLACK; 8*5=40 nats + stochastic growth stays < 88 (float overflow).
// SLACK=12 overflowed deterministically (8*12=96 > 88) -> inf -> NaN.
#define SLACK   5.0f
#define HALF    (8 * C_CLASS)      // floats per ring half (8 rows)

__device__ float        g_partial[NB];
__device__ unsigned int g_count;

#define CP16(d,s)  asm volatile("cp.async.ca.shared.global [%0], [%1], 16;" :: "r"(d), "l"(s))
#define CPCOMMIT() asm volatile("cp.async.commit_group;")
#define CPWAIT(N)  asm volatile("cp.async.wait_group %0;" :: "n"(N))

// One CTA per batch item; 4 warps split the 257-state chain (2 states/lane;
// warp3 lane31 also holds state 256). Warp w processes block k-w (lag chain).
// Boundary: producer lane31 stores pre-update a1 per step; consumer reads per
// step (broadcast LDS, lane-0 select). One __syncthreads per 8-step round.
__global__ void __launch_bounds__(128, 2) ctc_kernel(
    const float* __restrict__ log_probs,      // (T, N, C)
    const int*   __restrict__ targets,        // (N, S)
    const int*   __restrict__ input_lengths,  // (N,)
    const int*   __restrict__ target_lengths, // (N,)
    float*       __restrict__ out)
{
    __shared__ float ring[8 * HALF];          // 32 KB row ring
    __shared__ float bnd[3][4][8];            // [producer warp][blk&3][step]
    __shared__ float lsb[4][4];               // [warp][slot]: frame during block s
    __shared__ float sh[258];

    const int n    = blockIdx.x;
    const int w    = threadIdx.x >> 5;
    const int lane = threadIdx.x & 31;
    const float* lpn = log_probs + (size_t)n * C_CLASS;
    const char*  srcb = (const char*)lpn + lane * 16;
    const int inLen = input_lengths[n];
    const int steps = inLen - 1;
    const int K = steps >> 3, R = steps & 7;
    const unsigned ring_s = (unsigned)__cvta_generic_to_shared(ring);

    // One label per lane: odd state 64w+2*lane+1 -> targets[32w+lane]
    const int* tg = targets + n * S_TGT;
    const int e = tg[32 * w + lane];
    float sk;
    if (w == 0 && lane == 0) sk = 0.f;
    else sk = (e != tg[32 * w + lane - 1]) ? 1.f : 0.f;

    // states: a0 = even 64w+2l (blank), a1 = odd 64w+2l+1; a2 = state 256 (w3/l31)
    float a0 = 0.f, a1 = 0.f, a2 = 0.f;
    if (w == 0 && lane == 0) { a0 = __expf(lpn[0]); a1 = __expf(lpn[e]); }
    float ls = 0.f, lsB = 0.f, f = 1.f;

    // zero-init frame + boundary scratch
    if (threadIdx.x < 16)  ((float*)lsb)[threadIdx.x] = 0.f;
    if (threadIdx.x < 96)  ((float*)bnd)[threadIdx.x] = 0.f;

    // ---- prologue: warp 0 prefetches blocks 0..3 ----
    if (w == 0) {
        #pragma unroll
        for (int b = 0; b < 4; ++b) {
            unsigned d = ring_s + (unsigned)(b * (HALF * 4)) + lane * 16;
            const char* s = srcb + (size_t)(1 + 8 * b) * ROWB;
            #pragma unroll
            for (int q = 0; q < 8; ++q) CP16(d + q * 512, s + (size_t)q * ROWB);
            CPCOMMIT();
        }
    }
    __syncthreads();

    float lb = 0.f, r0 = 0.f;            // staged current row (blank lp, ratio)
    const int rounds = K + 4;
    for (int r = 0; r < rounds; ++r) {
        const int j = r - w;             // my block this round
        if (w == 0) CPWAIT(2);           // blocks <= r+1 resident

        if (j >= 0 && j <= K) {
            if (j == 0) {                // stage row 1 (block 0, slot 0)
                lb = ring[0];
                r0 = __expf(ring[e] - lb);
            }
            const float* ph = ring + (j & 7) * HALF;
            const float* bb = bnd[(w > 0) ? (w - 1) : 0][j & 3]; // producer's boundary
            float*       bw = bnd[(w < 3) ? w : 0][j & 3];       // my boundary out
            float fw = 0.f;
            if (w > 0) fw = __expf(lsb[w - 1][j & 3] - ls);

            if (j < K) {                 // ---- full 8-step block ----
                const float* pn = ring + ((j + 1) & 7) * HALF;
                #pragma unroll
                for (int u = 0; u < 8; ++u) {
                    float lbn, wv;
                    if (u < 7) { const int o = (u + 1) * C_CLASS;
                                 lbn = ph[o]; wv = ph[o + e]; }
                    else       { lbn = pn[0]; wv = pn[e]; }
                    float s0 = __expf(wv - lbn);
                    if (w < 3 && lane == 31) bw[u] = a1;   // pre-update boundary
                    float nbv = __shfl_up_sync(FULLM, a1, 1) * f;
                    if (w > 0) {
                        float cc = bb[u];                  // broadcast LDS
                        if (lane == 0) nbv = cc * fw;
                    } else {
                        if (lane == 0) nbv = 0.f;
                    }
                    lsB += lb;
                    float n0 = a0 + nbv;
                    float n1 = r0 * fmaf(sk, nbv, a0 + a1);
                    float n2 = a2 + a1;
                    a0 = n0; a1 = n1; a2 = n2;
                    lb = lbn; r0 = s0;
                }
                // ---- per-lane renorm + bounded-slack scan + cross-warp clamp ----
                {
                    float m = fmaxf(fmaxf(a0, a1), a2);
                    float lsc = (m > 0.f) ? (ls + __logf(m)) : -1e37f;
                    if (w > 0 && lane == 0)
                        lsc = fmaxf(lsc, lsb[w - 1][(j + 1) & 3] - SLACK);
                    float t1 = __shfl_up_sync(FULLM, lsc, 1);
                    if (lane >= 1)  lsc = fmaxf(lsc, t1 - SLACK);
                    float t2 = __shfl_up_sync(FULLM, lsc, 2);
                    if (lane >= 2)  lsc = fmaxf(lsc, t2 - 2.f * SLACK);
                    float t4 = __shfl_up_sync(FULLM, lsc, 4);
                    if (lane >= 4)  lsc = fmaxf(lsc, t4 - 4.f * SLACK);
                    float t8 = __shfl_up_sync(FULLM, lsc, 8);
                    if (lane >= 8)  lsc = fmaxf(lsc, t8 - 8.f * SLACK);
                    float t16 = __shfl_up_sync(FULLM, lsc, 16);
                    if (lane >= 16) lsc = fmaxf(lsc, t16 - 16.f * SLACK);
                    float sc = (m > 0.f) ? __expf(0.5f * (ls - lsc)) : 0.f;
                    a0 = (a0 * sc) * sc; a1 = (a1 * sc) * sc; a2 = (a2 * sc) * sc;
                    ls = lsc;
                    float lp = __shfl_up_sync(FULLM, ls, 1);
                    f = __expf(lp - ls);
                    if (w == 0 && lane == 0) f = 0.f;
                }
                if (lane == 31) lsb[w][(j + 1) & 3] = ls;  // frame during block j+1
            } else if (R > 0) {          // ---- remainder block (cold) ----
                for (int i = 0; i < R; ++i) {
                    const int o = (i + 1) * C_CLASS;
                    float lbn = ph[o], wv = ph[o + e];
                    float s0 = __expf(wv - lbn);
                    if (w < 3 && lane == 31) bw[i] = a1;
                    float nbv = __shfl_up_sync(FULLM, a1, 1) * f;
                    if (w > 0) { if (lane == 0) nbv = bb[i] * fw; }
                    else       { if (lane == 0) nbv = 0.f; }
                    lsB += lb;
                    float n0 = a0 + nbv;
                    float n1 = r0 * fmaf(sk, nbv, a0 + a1);
                    float n2 = a2 + a1;
                    a0 = n0; a1 = n1; a2 = n2;
                    lb = lbn; r0 = s0;
                }
            }
        }

        if (w == 0) {                    // prefetch block r+4
            const int b = r + 4;
            unsigned d = ring_s + (unsigned)((b & 7) * (HALF * 4)) + lane * 16;
            const int rs = 1 + 8 * b;
            if (rs + 7 <= T_LEN - 1) {
                const char* s = srcb + (size_t)rs * ROWB;
                #pragma unroll
                for (int q = 0; q < 8; ++q) CP16(d + q * 512, s + (size_t)q * ROWB);
            } else {
                #pragma unroll
                for (int q = 0; q < 8; ++q) {
                    int rr = rs + q; if (rr > T_LEN - 1) rr = T_LEN - 1;
                    CP16(d + q * 512, srcb + (size_t)rr * ROWB);
                }
            }
            CPCOMMIT();
        }
        __syncthreads();
    }
    if (w == 0) CPWAIT(0);

    // ---- extraction ----
    const float lt = ls + lsB;
    sh[64 * w + 2 * lane]     = (a0 > 0.f) ? __logf(a0) + lt : NEGV;
    sh[64 * w + 2 * lane + 1] = (a1 > 0.f) ? __logf(a1) + lt : NEGV;
    if (w == 3 && lane == 31) sh[256] = (a2 > 0.f) ? __logf(a2) + lt : NEGV;
    __syncthreads();

    if (w == 0) {
        if (lane == 0) {
            int tl  = target_lengths[n];
            int idx = 2 * tl;
            float la = sh[idx], lb2 = sh[idx - 1];
            float mm = fmaxf(la, lb2);
            float lse = mm + __logf(__expf(la - mm) + __expf(lb2 - mm));
            g_partial[n] = -lse / (float)tl;
            __threadfence();
        }
        __syncwarp();
        unsigned tk = 0;
        if (lane == 0) tk = atomicAdd(&g_count, 1u);
        tk = __shfl_sync(FULLM, tk, 0);
        if (tk == NB - 1) {              // last-arriving CTA reduces
            __threadfence();
            float s = 0.f;
            #pragma unroll
            for (int i = 0; i < NB / 32; ++i)
                s += __ldcg(&g_partial[lane + 32 * i]);
            #pragma unroll
            for (int o = 16; o > 0; o >>= 1)
                s += __shfl_down_sync(FULLM, s, o);
            if (lane == 0) {
                out[0] = s * (1.f / (float)NB);
                g_count = 0;             // reset for next graph replay
            }
        }
    }
}

extern "C" void kernel_launch(void* const* d_in, const int* in_sizes, int n_in,
                              void* d_out, int out_size)
{
    const float* log_probs      = (const float*)d_in[0];
    const int*   targets        = (const int*)  d_in[1];
    const int*   input_lengths  = (const int*)  d_in[2];
    const int*   target_lengths = (const int*)  d_in[3];

    ctc_kernel<<<NB, 128>>>(log_probs, targets, input_lengths,
                            target_lengths, (float*)d_out);
}

// round 14
// speedup vs baseline: 2.1671x; 2.1671x over previous
#include <cuda_runtime.h>
#include <cstdint>

#define T_LEN   1024
#define NB      256
#define C_CLASS 128
#define S_TGT   128
#define NCF     (NB * C_CLASS)
#define ROWB    (NCF * 4)
#define NEGV    -1e30f
#define FULLM   0xffffffffu
#define SLACK   12.0f
#define HALF    (8 * C_CLASS)      // floats per ring half (8 rows)

__device__ float        g_partial[NB];
__device__ unsigned int g_count;

#define CP16(d,s)  asm volatile("cp.async.ca.shared.global [%0], [%1], 16;" :: "r"(d), "l"(s))
#define CPCOMMIT() asm volatile("cp.async.commit_group;")
#define CPWAIT(N)  asm volatile("cp.async.wait_group %0;" :: "n"(N))

// ---------------- forward: alpha over t = 1..tm (R8-proven layout) ----------
// On return, sa[0..256] (overlaying this warp's ring) holds log alpha_tm.
__device__ __forceinline__ void run_fwd(
    const float* lpn, const int* tg, int tm,
    float* ring, unsigned ring_s, const char* srcb, float* sa, int lane)
{
    int4 tv = *(const int4*)(tg + 4 * lane);
    const int e0 = tv.x, e1 = tv.y, e2 = tv.z, e3 = tv.w;
    const int prev = (lane == 0) ? -1 : tg[4 * lane - 1];
    const float sk0 = (lane > 0 && e0 != prev) ? 1.f : 0.f;
    const float sk1 = (e1 != e0) ? 1.f : 0.f;
    const float sk2 = (e2 != e1) ? 1.f : 0.f;
    const float sk3 = (e3 != e2) ? 1.f : 0.f;

    float a0=0.f,a1=0.f,a2=0.f,a3=0.f,a4=0.f,a5=0.f,a6=0.f,a7=0.f,a8=0.f;
    if (lane == 0) { a0 = __expf(lpn[0]); a1 = __expf(lpn[e0]); }
    float ls = 0.f, lsB = 0.f, f = (lane == 0) ? 0.f : 1.f;

#define FSTEP(lbn,w0,w1,w2,w3) do {                                            \
    float s0=__expf((w0)-(lbn)), s1=__expf((w1)-(lbn));                        \
    float s2=__expf((w2)-(lbn)), s3=__expf((w3)-(lbn));                        \
    lsB += lb;                                                                 \
    float nb = __shfl_up_sync(FULLM, a7, 1) * f;                               \
    float n0 = a0 + nb;                                                        \
    float n1 = r0 * fmaf(sk0, nb, a0 + a1);                                    \
    float n2 = a2 + a1;                                                        \
    float n3 = r1 * fmaf(sk1, a1, a2 + a3);                                    \
    float n4 = a4 + a3;                                                        \
    float n5 = r2 * fmaf(sk2, a3, a4 + a5);                                    \
    float n6 = a6 + a5;                                                        \
    float n7 = r3 * fmaf(sk3, a5, a6 + a7);                                    \
    float n8 = a8 + a7;                                                        \
    a0=n0;a1=n1;a2=n2;a3=n3;a4=n4;a5=n5;a6=n6;a7=n7;a8=n8;                     \
    lb=(lbn); r0=s0; r1=s1; r2=s2; r3=s3;                                      \
} while (0)

    #pragma unroll
    for (int k = 0; k < 3; ++k) {                 // rows 1..24
        unsigned d = ring_s + (unsigned)(k * (HALF * 4)) + lane * 16;
        const char* s = srcb + (size_t)(1 + 8 * k) * ROWB;
        #pragma unroll
        for (int j = 0; j < 8; ++j) CP16(d + j * 512, s + (size_t)j * ROWB);
        CPCOMMIT();
    }
    CPWAIT(1);
    float lb = ring[0];
    float r0 = __expf(ring[e0] - lb), r1 = __expf(ring[e1] - lb);
    float r2 = __expf(ring[e2] - lb), r3 = __expf(ring[e3] - lb);

    const int end = tm + 1;                       // steps tt = 1..tm
    int t = 1, h = 0;
    while (t + 8 <= end) {
        const int nh = (h == 2) ? 0 : h + 1;
        const float* ph = ring + h * HALF;
        const float* pn = ring + nh * HALF;
        #pragma unroll
        for (int u = 0; u < 8; ++u) {
            float lbn, w0, w1, w2, w3;
            if (u < 7) { int o = (u + 1) * C_CLASS;
                lbn = ph[o]; w0 = ph[o+e0]; w1 = ph[o+e1]; w2 = ph[o+e2]; w3 = ph[o+e3]; }
            else { lbn = pn[0]; w0 = pn[e0]; w1 = pn[e1]; w2 = pn[e2]; w3 = pn[e3]; }
            FSTEP(lbn, w0, w1, w2, w3);
        }
        {   // prefetch rows t+24..t+31 into half h
            unsigned d = ring_s + (unsigned)(h * (HALF * 4)) + lane * 16;
            int rs = t + 24;
            #pragma unroll
            for (int j = 0; j < 8; ++j) {
                int rr = rs + j; if (rr > T_LEN - 1) rr = T_LEN - 1;
                CP16(d + j * 512, srcb + (size_t)rr * ROWB);
            }
            CPCOMMIT();
        }
        {   // per-lane renorm + upward bounded-slack scan
            float m = fmaxf(fmaxf(fmaxf(a0,a1),fmaxf(a2,a3)),
                            fmaxf(fmaxf(a4,a5),fmaxf(a6,a7)));
            m = fmaxf(m, a8);
            float lsc = (m > 0.f) ? (ls + __logf(m)) : -1e37f;
            float x;
            x=__shfl_up_sync(FULLM,lsc,1);  if(lane>=1)  lsc=fmaxf(lsc,x-SLACK);
            x=__shfl_up_sync(FULLM,lsc,2);  if(lane>=2)  lsc=fmaxf(lsc,x-2.f*SLACK);
            x=__shfl_up_sync(FULLM,lsc,4);  if(lane>=4)  lsc=fmaxf(lsc,x-4.f*SLACK);
            x=__shfl_up_sync(FULLM,lsc,8);  if(lane>=8)  lsc=fmaxf(lsc,x-8.f*SLACK);
            x=__shfl_up_sync(FULLM,lsc,16); if(lane>=16) lsc=fmaxf(lsc,x-16.f*SLACK);
            float sc = (m > 0.f) ? __expf(0.5f * (ls - lsc)) : 0.f;
            a0=(a0*sc)*sc;a1=(a1*sc)*sc;a2=(a2*sc)*sc;a3=(a3*sc)*sc;a4=(a4*sc)*sc;
            a5=(a5*sc)*sc;a6=(a6*sc)*sc;a7=(a7*sc)*sc;a8=(a8*sc)*sc;
            ls = lsc;
            float lp = __shfl_up_sync(FULLM, ls, 1);
            f = (lane == 0) ? 0.f : __expf(lp - ls);
        }
        t += 8; h = nh;
        CPWAIT(1);
    }
    for (int tt = t; tt < end; ++tt) {            // remainder (<8 steps)
        int r = tt + 1; if (r > T_LEN - 1) r = T_LEN - 1;
        int b = (r - 1) >> 3;
        const float* q = ring + (b % 3) * HALF + ((r - 1) & 7) * C_CLASS;
        FSTEP(q[0], q[e0], q[e1], q[e2], q[e3]);
    }
    CPWAIT(0);
    __syncwarp();                                 // ring reads done before overlay
    const float lt = ls + lsB;
    sa[8*lane+0]=(a0>0.f)?__logf(a0)+lt:NEGV;
    sa[8*lane+1]=(a1>0.f)?__logf(a1)+lt:NEGV;
    sa[8*lane+2]=(a2>0.f)?__logf(a2)+lt:NEGV;
    sa[8*lane+3]=(a3>0.f)?__logf(a3)+lt:NEGV;
    sa[8*lane+4]=(a4>0.f)?__logf(a4)+lt:NEGV;
    sa[8*lane+5]=(a5>0.f)?__logf(a5)+lt:NEGV;
    sa[8*lane+6]=(a6>0.f)?__logf(a6)+lt:NEGV;
    sa[8*lane+7]=(a7>0.f)?__logf(a7)+lt:NEGV;
    if (lane == 31) sa[256]=(a8>0.f)?__logf(a8)+lt:NEGV;
#undef FSTEP
}

// ---------------- backward: beta over t = inLen-1 .. tm+1 -------------------
// On return, sb[0..258] (overlaying this warp's ring) holds log beta_{tm+1}.
__device__ __forceinline__ void run_bwd(
    const float* lpn, const int* tg, int tm, int inLen, int TL,
    float* ring, unsigned ring_s, const char* srcb, float* sb, int lane)
{
    int4 tv = *(const int4*)(tg + 4 * lane);
    const int e0 = tv.x, e1 = tv.y, e2 = tv.z, e3 = tv.w;
    const int eN = (lane < 31) ? tg[4 * lane + 4] : 0;
    const float K1 = (e1 != e0) ? 1.f : 0.f;
    const float K2 = (e2 != e1) ? 1.f : 0.f;
    const float K3 = (e3 != e2) ? 1.f : 0.f;
    const float K4 = (lane < 31 && eN != e3) ? 1.f : 0.f;

    float b0=0.f,b1=0.f,b2=0.f,b3=0.f,b4=0.f,b5=0.f,b6=0.f,b7=0.f,b8=0.f;
    float ls = 0.f, f = 1.f;
    // init from row inLen-1: beta = emit at final states {2TL, 2TL-1}
    const float* rl = lpn + (size_t)(inLen - 1) * NCF;
    const float lbl = __ldg(rl);
    float lsB = lbl;                              // blank factored at init row
    {
        const int fin = 2 * TL, l0 = 8 * lane;
        int d = fin - l0;
        if (d >= 0 && d < 8) { if (d==0) b0=1.f; else if (d==2) b2=1.f;
                               else if (d==4) b4=1.f; else if (d==6) b6=1.f; }
        int d1 = fin - 1 - l0;
        if (d1 >= 0 && d1 < 8) {
            int ee = (d1==1)?e0:(d1==3)?e1:(d1==5)?e2:e3;
            float rr = __expf(__ldg(rl + ee) - lbl);
            if (d1==1) b1=rr; else if (d1==3) b3=rr;
            else if (d1==5) b5=rr; else b7=rr;
        }
        if (lane == 31 && fin == 256) b8 = 1.f;
    }

#define BSTEP(lbn,w0,w1,w2,w3) do {                                            \
    float s0=__expf((w0)-(lbn)), s1=__expf((w1)-(lbn));                        \
    float s2=__expf((w2)-(lbn)), s3=__expf((w3)-(lbn));                        \
    lsB += lb;                                                                 \
    float c0 = __shfl_down_sync(FULLM, b0, 1);                                 \
    float c1 = __shfl_down_sync(FULLM, b1, 1);                                 \
    if (lane == 31) { c0 = b8; c1 = 0.f; } else { c0 *= f; c1 *= f; }          \
    float n0 = b0 + b1;                                                        \
    float n1 = r0 * fmaf(K1, b3, b1 + b2);                                     \
    float n2 = b2 + b3;                                                        \
    float n3 = r1 * fmaf(K2, b5, b3 + b4);                                     \
    float n4 = b4 + b5;                                                        \
    float n5 = r2 * fmaf(K3, b7, b5 + b6);                                     \
    float n6 = b6 + b7;                                                        \
    float n7 = r3 * fmaf(K4, c1, b7 + c0);                                     \
    float n8 = b8;                                                             \
    b0=n0;b1=n1;b2=n2;b3=n3;b4=n4;b5=n5;b6=n6;b7=n7;b8=n8;                     \
    lb=(lbn); r0=s0; r1=s1; r2=s2; r3=s3;                                      \
} while (0)

    // row(v) = inLen-2-v, stored at half (v>>3)%3, slot v&7
    #pragma unroll
    for (int k = 0; k < 3; ++k) {
        unsigned d = ring_s + (unsigned)(k * (HALF * 4)) + lane * 16;
        #pragma unroll
        for (int j = 0; j < 8; ++j) {
            int row = inLen - 2 - (8 * k + j); if (row < 0) row = 0;
            CP16(d + j * 512, srcb + (size_t)row * ROWB);
        }
        CPCOMMIT();
    }
    CPWAIT(1);
    float lb = ring[0];
    float r0 = __expf(ring[e0] - lb), r1 = __expf(ring[e1] - lb);
    float r2 = __expf(ring[e2] - lb), r3 = __expf(ring[e3] - lb);

    const int S = inLen - 2 - tm;                 // steps v = 0..S-1
    int v = 0, h = 0;
    while (v + 8 <= S) {
        const int nh = (h == 2) ? 0 : h + 1;
        const float* ph = ring + h * HALF;
        const float* pn = ring + nh * HALF;
        #pragma unroll
        for (int u = 0; u < 8; ++u) {
            float lbn, w0, w1, w2, w3;
            if (u < 7) { int o = (u + 1) * C_CLASS;
                lbn = ph[o]; w0 = ph[o+e0]; w1 = ph[o+e1]; w2 = ph[o+e2]; w3 = ph[o+e3]; }
            else { lbn = pn[0]; w0 = pn[e0]; w1 = pn[e1]; w2 = pn[e2]; w3 = pn[e3]; }
            BSTEP(lbn, w0, w1, w2, w3);
        }
        {   // prefetch block v/8+3 into half h
            unsigned d = ring_s + (unsigned)(h * (HALF * 4)) + lane * 16;
            int bk = (v >> 3) + 3;
            #pragma unroll
            for (int j = 0; j < 8; ++j) {
                int row = inLen - 2 - (8 * bk + j); if (row < 0) row = 0;
                CP16(d + j * 512, srcb + (size_t)row * ROWB);
            }
            CPCOMMIT();
        }
        {   // per-lane renorm + DOWNWARD bounded-slack scan
            float m = fmaxf(fmaxf(fmaxf(b0,b1),fmaxf(b2,b3)),
                            fmaxf(fmaxf(b4,b5),fmaxf(b6,b7)));
            m = fmaxf(m, b8);
            float lsc = (m > 0.f) ? (ls + __logf(m)) : -1e37f;
            float x;
            x=__shfl_down_sync(FULLM,lsc,1);  if(lane<=30) lsc=fmaxf(lsc,x-SLACK);
            x=__shfl_down_sync(FULLM,lsc,2);  if(lane<=29) lsc=fmaxf(lsc,x-2.f*SLACK);
            x=__shfl_down_sync(FULLM,lsc,4);  if(lane<=27) lsc=fmaxf(lsc,x-4.f*SLACK);
            x=__shfl_down_sync(FULLM,lsc,8);  if(lane<=23) lsc=fmaxf(lsc,x-8.f*SLACK);
            x=__shfl_down_sync(FULLM,lsc,16); if(lane<=15) lsc=fmaxf(lsc,x-16.f*SLACK);
            float sc = (m > 0.f) ? __expf(0.5f * (ls - lsc)) : 0.f;
            b0=(b0*sc)*sc;b1=(b1*sc)*sc;b2=(b2*sc)*sc;b3=(b3*sc)*sc;b4=(b4*sc)*sc;
            b5=(b5*sc)*sc;b6=(b6*sc)*sc;b7=(b7*sc)*sc;b8=(b8*sc)*sc;
            ls = lsc;
            float lp = __shfl_down_sync(FULLM, ls, 1);
            f = (lane == 31) ? 0.f : __expf(lp - ls);
        }
        v += 8; h = nh;
        CPWAIT(1);
    }
    for (int vv = v; vv < S; ++vv) {              // remainder (<8 steps)
        int vn = vv + 1;
        const float* q = ring + ((vn >> 3) % 3) * HALF + (vn & 7) * C_CLASS;
        BSTEP(q[0], q[e0], q[e1], q[e2], q[e3]);
    }
    CPWAIT(0);
    __syncwarp();                                 // ring reads done before overlay
    const float lt = ls + lsB;
    sb[8*lane+0]=(b0>0.f)?__logf(b0)+lt:NEGV;
    sb[8*lane+1]=(b1>0.f)?__logf(b1)+lt:NEGV;
    sb[8*lane+2]=(b2>0.f)?__logf(b2)+lt:NEGV;
    sb[8*lane+3]=(b3>0.f)?__logf(b3)+lt:NEGV;
    sb[8*lane+4]=(b4>0.f)?__logf(b4)+lt:NEGV;
    sb[8*lane+5]=(b5>0.f)?__logf(b5)+lt:NEGV;
    sb[8*lane+6]=(b6>0.f)?__logf(b6)+lt:NEGV;
    sb[8*lane+7]=(b7>0.f)?__logf(b7)+lt:NEGV;
    if (lane == 31) { sb[256]=(b8>0.f)?__logf(b8)+lt:NEGV; }
    if (lane == 0)  { sb[257]=NEGV; sb[258]=NEGV; }
#undef BSTEP
}

__global__ void __launch_bounds__(128) ctc_kernel(
    const float* __restrict__ log_probs,
    const int*   __restrict__ targets,
    const int*   __restrict__ input_lengths,
    const int*   __restrict__ target_lengths,
    float*       __restrict__ out)
{
    // 4 warps x 3 halves = 48KB exactly. After each warp's final CPWAIT(0),
    // its ring is dead and is overlaid with the 257-entry log-alpha/beta
    // vector for the combine (no extra shared memory).
    __shared__ float ringall[4][3 * HALF];

    const int wid  = threadIdx.x >> 5;
    const int lane = threadIdx.x & 31;
    const int p    = wid >> 1;
    const bool bwd = wid & 1;
    const int n    = blockIdx.x * 2 + p;

    const float* lpn = log_probs + (size_t)n * C_CLASS;
    const int*   tg  = targets + n * S_TGT;
    const int inLen  = input_lengths[n];
    const int TL     = target_lengths[n];
    const int tm     = (inLen - 1) >> 1;          // fwd: 1..tm, bwd: inLen-1..tm+1

    float* ring = ringall[wid];
    const unsigned ring_s = (unsigned)__cvta_generic_to_shared(ring);
    const char* srcb = (const char*)lpn + lane * 16;

    if (!bwd) run_fwd(lpn, tg, tm, ring, ring_s, srcb, ring, lane);
    else      run_bwd(lpn, tg, tm, inLen, TL, ring, ring_s, srcb, ring, lane);
    __syncthreads();

    if (!bwd) {
        // ---- combine: P = sum_l alpha_tm(l) * (b(l)+b(l+1)+skip(l+2)*b(l+2)) ----
        const float* sa = ringall[2 * p];
        const float* sb = ringall[2 * p + 1];
        int4 tv = *(const int4*)(tg + 4 * lane);
        const int e0 = tv.x, e1 = tv.y, e2 = tv.z, e3 = tv.w;
        const float g1 = (e1 != e0) ? 1.f : 0.f;          // flag of state 8L+3
        const float g2 = (e2 != e1) ? 1.f : 0.f;          // 8L+5
        const float g3 = (e3 != e2) ? 1.f : 0.f;          // 8L+7
        const float g4 = (lane < 31 && tg[4*lane+4] != e3) ? 1.f : 0.f; // 8(L+1)+1
        float E[8];
        const int l0 = 8 * lane;
        #pragma unroll
        for (int j = 0; j < 8; ++j) {
            float fl = (j==1)?g1 : (j==3)?g2 : (j==5)?g3 : (j==7)?g4 : 0.f;
            float x0 = sb[l0 + j];
            float x1 = sb[l0 + j + 1];
            float x2 = (fl > 0.f) ? sb[l0 + j + 2] : NEGV;
            float m3 = fmaxf(x0, fmaxf(x1, x2));
            float lse = m3 + __logf(__expf(x0-m3) + __expf(x1-m3) + __expf(x2-m3));
            E[j] = sa[l0 + j] + lse;
        }
        float E8 = (lane == 31) ? (sa[256] + sb[256]) : NEGV;
        float mx = E8;
        #pragma unroll
        for (int j = 0; j < 8; ++j) mx = fmaxf(mx, E[j]);
        #pragma unroll
        for (int o = 16; o > 0; o >>= 1)
            mx = fmaxf(mx, __shfl_xor_sync(FULLM, mx, o));
        float s = __expf(E8 - mx);
        #pragma unroll
        for (int j = 0; j < 8; ++j) s += __expf(E[j] - mx);
        #pragma unroll
        for (int o = 16; o > 0; o >>= 1)
            s += __shfl_xor_sync(FULLM, s, o);
        if (lane == 0) {
            float loss = -(mx + __logf(s));
            g_partial[n] = loss / (float)TL;
            __threadfence();
        }
        __syncwarp();
        unsigned tk = 0;
        if (lane == 0) tk = atomicAdd(&g_count, 1u);
        tk = __shfl_sync(FULLM, tk, 0);
        if (tk == NB - 1) {                        // last problem's fwd warp reduces
            __threadfence();
            float acc = 0.f;
            #pragma unroll
            for (int i = 0; i < NB / 32; ++i)
                acc += __ldcg(&g_partial[lane + 32 * i]);
            #pragma unroll
            for (int o = 16; o > 0; o >>= 1)
                acc += __shfl_down_sync(FULLM, acc, o);
            if (lane == 0) {
                out[0] = acc * (1.f / (float)NB);
                g_count = 0;
            }
        }
    }
}

extern "C" void kernel_launch(void* const* d_in, const int* in_sizes, int n_in,
                              void* d_out, int out_size)
{
    const float* log_probs      = (const float*)d_in[0];
    const int*   targets        = (const int*)  d_in[1];
    const int*   input_lengths  = (const int*)  d_in[2];
    const int*   target_lengths = (const int*)  d_in[3];

    ctc_kernel<<<NB / 2, 128>>>(log_probs, targets, input_lengths,
                                target_lengths, (float*)d_out);
}